// round 3
// baseline (speedup 1.0000x reference)
#include <cuda_runtime.h>
#include <cuda_bf16.h>
#include <math.h>

#define HID   768
#define INTER 1536
#define DK    128
#define BATCH 4
#define SEQ   2048
#define MTOT  (BATCH*SEQ)          // 8192
#define NCOLS (2*INTER+DK)         // 3200
#define LOG512F 6.2383246250395075f
#define GEMM_SMEM (2*4*512*16)     // 64 KB: 2 stages x 4 tiles x 8KB

typedef unsigned short u16;

// ---------------- scratch (device globals) ---------------------------------
__device__ u16   g_Hh[(size_t)MTOT*HID],   g_Hl[(size_t)MTOT*HID];
__device__ u16   g_Wih[(size_t)HID*NCOLS], g_Wil[(size_t)HID*NCOLS];
__device__ u16   g_Woh[(size_t)INTER*HID], g_Wol[(size_t)INTER*HID];
__device__ float g_u[(size_t)MTOT*INTER];
__device__ u16   g_vh[(size_t)MTOT*INTER], g_vl[(size_t)MTOT*INTER];
__device__ u16   g_qh[(size_t)MTOT*DK],    g_ql[(size_t)MTOT*DK];
__device__ u16   g_kh[(size_t)MTOT*DK],    g_kl[(size_t)MTOT*DK];
__device__ float g_A [(size_t)BATCH*SEQ*SEQ];
__device__ u16   g_Ah[(size_t)BATCH*SEQ*SEQ], g_Al[(size_t)BATCH*SEQ*SEQ];
__device__ u16   g_th[(size_t)MTOT*INTER], g_tl[(size_t)MTOT*INTER];

// ---------------- PTX helpers ----------------------------------------------
__device__ __forceinline__ void mma16816(float c[4], const unsigned a[4], const unsigned b[2]) {
    asm volatile(
        "mma.sync.aligned.m16n8k16.row.col.f32.bf16.bf16.f32 "
        "{%0,%1,%2,%3}, {%4,%5,%6,%7}, {%8,%9}, {%0,%1,%2,%3};\n"
        : "+f"(c[0]), "+f"(c[1]), "+f"(c[2]), "+f"(c[3])
        : "r"(a[0]), "r"(a[1]), "r"(a[2]), "r"(a[3]), "r"(b[0]), "r"(b[1]));
}
__device__ __forceinline__ void ldsm4(unsigned r[4], unsigned addr) {
    asm volatile("ldmatrix.sync.aligned.m8n8.x4.shared.b16 {%0,%1,%2,%3}, [%4];\n"
        : "=r"(r[0]), "=r"(r[1]), "=r"(r[2]), "=r"(r[3]) : "r"(addr));
}
__device__ __forceinline__ void ldsm4t(unsigned r[4], unsigned addr) {
    asm volatile("ldmatrix.sync.aligned.m8n8.x4.trans.shared.b16 {%0,%1,%2,%3}, [%4];\n"
        : "=r"(r[0]), "=r"(r[1]), "=r"(r[2]), "=r"(r[3]) : "r"(addr));
}
__device__ __forceinline__ void cp16(void* dst, const void* src) {
    unsigned d = (unsigned)__cvta_generic_to_shared(dst);
    asm volatile("cp.async.cg.shared.global [%0], [%1], 16;\n" :: "r"(d), "l"(src));
}
__device__ __forceinline__ void splitf(float x, u16& h, u16& l) {
    __nv_bfloat16 hb = __float2bfloat16(x);
    h = __bfloat16_as_ushort(hb);
    l = __bfloat16_as_ushort(__float2bfloat16(x - __bfloat162float(hb)));
}

// ---------------- input pre-split kernel ------------------------------------
__global__ __launch_bounds__(256)
void k_splitsel(const float4* __restrict__ src, int which, int n4)
{
    int i = blockIdx.x * 256 + threadIdx.x;
    if (i >= n4) return;
    ushort4* h4; ushort4* l4;
    if (which == 0)      { h4 = (ushort4*)g_Hh;  l4 = (ushort4*)g_Hl;  }
    else if (which == 1) { h4 = (ushort4*)g_Wih; l4 = (ushort4*)g_Wil; }
    else                 { h4 = (ushort4*)g_Woh; l4 = (ushort4*)g_Wol; }
    float4 f = src[i];
    ushort4 H, L;
    splitf(f.x, H.x, L.x); splitf(f.y, H.y, L.y);
    splitf(f.z, H.z, L.z); splitf(f.w, H.w, L.w);
    h4[i] = H; l4[i] = L;
}

// ---------------- tile stagers (cp.async) -----------------------------------
// A-style tile: 128 rows x 32 k, bf16, row stride 64B (4 chunks), swizzle c^=(row>>1)&3
__device__ __forceinline__ void stage_tileA(uint4* dst, const u16* __restrict__ g,
                                            int ld, int tid) {
    #pragma unroll
    for (int r = 0; r < 2; r++) {
        int c = tid + r * 256;
        int row = c >> 2, kc = c & 3;
        cp16(dst + row * 4 + (kc ^ ((row >> 1) & 3)),
             g + (size_t)row * ld + kc * 8);
    }
}
// B-style tile: 32 k-rows x 128 n, bf16, row stride 256B (16 chunks), swizzle c^=k&7
__device__ __forceinline__ void stage_tileB(uint4* dst, const u16* __restrict__ g,
                                            int ld, int tid) {
    #pragma unroll
    for (int r = 0; r < 2; r++) {
        int c = tid + r * 256;
        int k = c >> 4, nc = c & 15;
        cp16(dst + k * 16 + (nc ^ (k & 7)),
             g + (size_t)k * ld + nc * 8);
    }
}

// ---------------- bf16x3 tensor-core GEMM body (pre-split operands) ---------
// 128x128 CTA tile, BK=32, 256 threads, warps 2(m) x 4(n), warp tile 64x32.
// 2-stage cp.async pipeline. BT=true: B stored [N][K] (Q@K^T).
template<bool BT>
__device__ __forceinline__ void mma_gemm_pk(const u16* __restrict__ Ah, const u16* __restrict__ Al, int lda,
                                            const u16* __restrict__ Bh, const u16* __restrict__ Bl, int ldb,
                                            int K, int rowBase, int colBase,
                                            float acc[4][4][4])
{
    extern __shared__ __align__(16) uint4 smdyn[];
    const int tid = threadIdx.x;
    const int lane = tid & 31, w = tid >> 5;
    const int wm = w >> 2, wn = w & 3;
    const int g = lane >> 3, i = lane & 7;
    const int nsteps = K / 32;

    auto issue = [&](int step) {
        uint4* st = smdyn + (step & 1) * 2048;
        int k0 = step * 32;
        stage_tileA(st,        Ah + (size_t)rowBase * lda + k0, lda, tid);
        stage_tileA(st + 512,  Al + (size_t)rowBase * lda + k0, lda, tid);
        if (BT) {
            stage_tileA(st + 1024, Bh + (size_t)colBase * ldb + k0, ldb, tid);
            stage_tileA(st + 1536, Bl + (size_t)colBase * ldb + k0, ldb, tid);
        } else {
            stage_tileB(st + 1024, Bh + (size_t)k0 * ldb + colBase, ldb, tid);
            stage_tileB(st + 1536, Bl + (size_t)k0 * ldb + colBase, ldb, tid);
        }
        asm volatile("cp.async.commit_group;\n");
    };

    issue(0);
    for (int step = 0; step < nsteps; step++) {
        if (step + 1 < nsteps) {
            issue(step + 1);
            asm volatile("cp.async.wait_group 1;\n");
        } else {
            asm volatile("cp.async.wait_group 0;\n");
        }
        __syncthreads();

        const uint4* st = smdyn + (step & 1) * 2048;
        const unsigned bAh = (unsigned)__cvta_generic_to_shared(st);
        const unsigned bAl = bAh + 8192;
        const unsigned bBh = bAh + 16384;
        const unsigned bBl = bAh + 24576;

        #pragma unroll
        for (int ks = 0; ks < 32; ks += 16) {
            unsigned aH[4][4], aL[4][4];
            #pragma unroll
            for (int mi = 0; mi < 4; mi++) {
                int mrow = wm * 64 + mi * 16 + (g & 1) * 8 + i;
                int ch = (ks >> 3) + (g >> 1);
                int off = mrow * 64 + ((ch ^ ((mrow >> 1) & 3)) << 4);
                ldsm4(aH[mi], bAh + off);
                ldsm4(aL[mi], bAl + off);
            }
            unsigned bH[4][2], bL[4][2];
            #pragma unroll
            for (int p = 0; p < 2; p++) {
                unsigned rh[4], rl[4];
                if (BT) {
                    int nrow = wn * 32 + p * 16 + (g >> 1) * 8 + i;
                    int ch = (ks >> 3) + (g & 1);
                    int off = nrow * 64 + ((ch ^ ((nrow >> 1) & 3)) << 4);
                    ldsm4(rh, bBh + off);
                    ldsm4(rl, bBl + off);
                } else {
                    int kr = ks + (g & 1) * 8 + i;
                    int nl = wn * 32 + p * 16 + (g >> 1) * 8;
                    int off = kr * 256 + ((((nl >> 3) ^ (kr & 7))) << 4);
                    ldsm4t(rh, bBh + off);
                    ldsm4t(rl, bBl + off);
                }
                bH[2*p][0] = rh[0]; bH[2*p][1] = rh[1];
                bH[2*p+1][0] = rh[2]; bH[2*p+1][1] = rh[3];
                bL[2*p][0] = rl[0]; bL[2*p][1] = rl[1];
                bL[2*p+1][0] = rl[2]; bL[2*p+1][1] = rl[3];
            }
            #pragma unroll
            for (int mi = 0; mi < 4; mi++)
                #pragma unroll
                for (int ng = 0; ng < 4; ng++) {
                    mma16816(acc[mi][ng], aH[mi], bH[ng]);
                    mma16816(acc[mi][ng], aH[mi], bL[ng]);
                    mma16816(acc[mi][ng], aL[mi], bH[ng]);
                }
        }
        __syncthreads();
    }
}

#define EPI_SETUP() \
    const int lane = threadIdx.x & 31, w = threadIdx.x >> 5; \
    const int wm = w >> 2, wn = w & 3; \
    const int er = lane >> 2, ec = (lane & 3) * 2;

// ---------------- kernel 1: GEMM1 + SiLU + split ---------------------------
__global__ __launch_bounds__(256)
void k_gemm1(const float* __restrict__ qg, const float* __restrict__ kg)
{
    float acc[4][4][4] = {};
    const int rowBase = blockIdx.y * 128, colBase = blockIdx.x * 128;
    mma_gemm_pk<false>(g_Hh, g_Hl, HID, g_Wih, g_Wil, NCOLS, HID, rowBase, colBase, acc);
    EPI_SETUP();
    #pragma unroll
    for (int mi = 0; mi < 4; mi++)
        #pragma unroll
        for (int ng = 0; ng < 4; ng++) {
            int r0 = rowBase + wm * 64 + mi * 16 + er;
            int c0 = colBase + wn * 32 + ng * 8 + ec;
            #pragma unroll
            for (int h = 0; h < 2; h++) {
                int row = r0 + h * 8;
                #pragma unroll
                for (int j = 0; j < 2; j++) {
                    int col = c0 + j;
                    float x = acc[mi][ng][h * 2 + j];
                    float v = x / (1.0f + __expf(-x));  // SiLU
                    if (col < INTER) {
                        g_u[(size_t)row * INTER + col] = v;
                    } else if (col < 2 * INTER) {
                        size_t idx = (size_t)row * INTER + (col - INTER);
                        splitf(v, g_vh[idx], g_vl[idx]);
                    } else {
                        int c = col - 2 * INTER;
                        size_t idx = (size_t)row * DK + c;
                        splitf(v * qg[c], g_qh[idx], g_ql[idx]);
                        splitf(v * kg[c], g_kh[idx], g_kl[idx]);
                    }
                }
            }
        }
}

// ---------------- kernel 2: Q @ K^T / sqrt(DK) -----------------------------
__global__ __launch_bounds__(256)
void k_qk()
{
    float acc[4][4][4] = {};
    const int b = blockIdx.z;
    const int rowBase = blockIdx.y * 128, colBase = blockIdx.x * 128;
    const size_t o = (size_t)b * SEQ * DK;
    mma_gemm_pk<true>(g_qh + o, g_ql + o, DK, g_kh + o, g_kl + o, DK,
                      DK, rowBase, colBase, acc);
    float* Ab = g_A + (size_t)b * SEQ * SEQ;
    const float sc = 0.08838834764831845f;  // 1/sqrt(128)
    EPI_SETUP();
    #pragma unroll
    for (int mi = 0; mi < 4; mi++)
        #pragma unroll
        for (int ng = 0; ng < 4; ng++) {
            int r0 = rowBase + wm * 64 + mi * 16 + er;
            int c0 = colBase + wn * 32 + ng * 8 + ec;
            *(float2*)&Ab[(size_t)r0 * SEQ + c0] =
                make_float2(acc[mi][ng][0] * sc, acc[mi][ng][1] * sc);
            *(float2*)&Ab[(size_t)(r0 + 8) * SEQ + c0] =
                make_float2(acc[mi][ng][2] * sc, acc[mi][ng][3] * sc);
        }
}

// ---------------- kernel 3: masked softmax, writes split bf16 --------------
__global__ __launch_bounds__(256)
void k_softmax(const int* __restrict__ mask)
{
    const int bm = blockIdx.x;
    const int b = bm >> 11;
    const int m = bm & (SEQ - 1);
    const int tid = threadIdx.x;

    __shared__ float sdata[SEQ];
    __shared__ float red[256];

    float ls = 0.f;
    for (int n = tid; n < SEQ; n += 256) ls += (float)mask[b * SEQ + n];
    red[tid] = ls; __syncthreads();
    for (int s = 128; s > 0; s >>= 1) {
        if (tid < s) red[tid] += red[tid + s];
        __syncthreads();
    }
    const float l = red[0];
    __syncthreads();
    const float scale = logf(fmaxf(l, 1.0f)) * (1.0f / LOG512F);

    const size_t rowoff = (size_t)b * SEQ * SEQ + (size_t)m * SEQ;
    const float* row = g_A + rowoff;

    float mx = -3.4e38f;
    for (int n = tid; n < SEQ; n += 256) {
        float a = row[n];
        if (mask[b * SEQ + n] == 0) a = -1e12f;
        a *= scale;
        sdata[n] = a;
        mx = fmaxf(mx, a);
    }
    red[tid] = mx; __syncthreads();
    for (int s = 128; s > 0; s >>= 1) {
        if (tid < s) red[tid] = fmaxf(red[tid], red[tid + s]);
        __syncthreads();
    }
    mx = red[0]; __syncthreads();

    float sm = 0.f;
    for (int n = tid; n < SEQ; n += 256) {
        float e = __expf(sdata[n] - mx);
        sdata[n] = e;
        sm += e;
    }
    red[tid] = sm; __syncthreads();
    for (int s = 128; s > 0; s >>= 1) {
        if (tid < s) red[tid] += red[tid + s];
        __syncthreads();
    }
    const float inv = 1.0f / red[0];
    __syncthreads();

    for (int n = tid; n < SEQ; n += 256)
        splitf(sdata[n] * inv, g_Ah[rowoff + n], g_Al[rowoff + n]);
}

// ---------------- kernel 4: (A @ V) * u, writes split t --------------------
__global__ __launch_bounds__(256)
void k_av()
{
    float acc[4][4][4] = {};
    const int b = blockIdx.z;
    const int rowBase = blockIdx.y * 128, colBase = blockIdx.x * 128;
    const size_t oa = (size_t)b * SEQ * SEQ;
    const size_t ov = (size_t)b * SEQ * INTER;
    mma_gemm_pk<false>(g_Ah + oa, g_Al + oa, SEQ, g_vh + ov, g_vl + ov, INTER,
                       SEQ, rowBase, colBase, acc);
    EPI_SETUP();
    #pragma unroll
    for (int mi = 0; mi < 4; mi++)
        #pragma unroll
        for (int ng = 0; ng < 4; ng++) {
            int r0 = rowBase + wm * 64 + mi * 16 + er;
            int c0 = colBase + wn * 32 + ng * 8 + ec;
            #pragma unroll
            for (int h = 0; h < 2; h++) {
                int row = r0 + h * 8;
                size_t base = ((size_t)(b * SEQ + row)) * INTER + c0;
                float2 u2 = *(const float2*)&g_u[base];
                splitf(u2.x * acc[mi][ng][h * 2],     g_th[base],     g_tl[base]);
                splitf(u2.y * acc[mi][ng][h * 2 + 1], g_th[base + 1], g_tl[base + 1]);
            }
        }
}

// ---------------- kernel 5: t @ Wo -> out ----------------------------------
__global__ __launch_bounds__(256)
void k_out(float* __restrict__ out)
{
    float acc[4][4][4] = {};
    const int rowBase = blockIdx.y * 128, colBase = blockIdx.x * 128;
    mma_gemm_pk<false>(g_th, g_tl, INTER, g_Woh, g_Wol, HID,
                       INTER, rowBase, colBase, acc);
    EPI_SETUP();
    #pragma unroll
    for (int mi = 0; mi < 4; mi++)
        #pragma unroll
        for (int ng = 0; ng < 4; ng++) {
            int r0 = rowBase + wm * 64 + mi * 16 + er;
            int c0 = colBase + wn * 32 + ng * 8 + ec;
            *(float2*)&out[(size_t)r0 * HID + c0] =
                make_float2(acc[mi][ng][0], acc[mi][ng][1]);
            *(float2*)&out[(size_t)(r0 + 8) * HID + c0] =
                make_float2(acc[mi][ng][2], acc[mi][ng][3]);
        }
}

// ---------------- launch ----------------------------------------------------
extern "C" void kernel_launch(void* const* d_in, const int* in_sizes, int n_in,
                              void* d_out, int out_size)
{
    const float* h    = (const float*)d_in[0];
    const float* Wi   = (const float*)d_in[1];
    const float* Wo   = (const float*)d_in[2];
    const float* qg   = (const float*)d_in[3];
    const float* kg   = (const float*)d_in[4];
    const int*   mask = (const int*)d_in[5];
    float*       out  = (float*)d_out;

    cudaFuncSetAttribute(k_gemm1, cudaFuncAttributeMaxDynamicSharedMemorySize, GEMM_SMEM);
    cudaFuncSetAttribute(k_qk,    cudaFuncAttributeMaxDynamicSharedMemorySize, GEMM_SMEM);
    cudaFuncSetAttribute(k_av,    cudaFuncAttributeMaxDynamicSharedMemorySize, GEMM_SMEM);
    cudaFuncSetAttribute(k_out,   cudaFuncAttributeMaxDynamicSharedMemorySize, GEMM_SMEM);

    int n4h  = MTOT * HID / 4;
    int n4wi = HID * NCOLS / 4;
    int n4wo = INTER * HID / 4;
    k_splitsel<<<(n4h  + 255) / 256, 256>>>((const float4*)h,  0, n4h);
    k_splitsel<<<(n4wi + 255) / 256, 256>>>((const float4*)Wi, 1, n4wi);
    k_splitsel<<<(n4wo + 255) / 256, 256>>>((const float4*)Wo, 2, n4wo);

    k_gemm1<<<dim3(NCOLS / 128, MTOT / 128), 256, GEMM_SMEM>>>(qg, kg);
    k_qk<<<dim3(SEQ / 128, SEQ / 128, BATCH), 256, GEMM_SMEM>>>();
    k_softmax<<<BATCH * SEQ, 256>>>(mask);
    k_av<<<dim3(INTER / 128, SEQ / 128, BATCH), 256, GEMM_SMEM>>>();
    k_out<<<dim3(HID / 128, MTOT / 128), 256, GEMM_SMEM>>>(out);
}

// round 5
// speedup vs baseline: 1.4565x; 1.4565x over previous
#include <cuda_runtime.h>
#include <cuda_bf16.h>
#include <math.h>

#define HID   768
#define INTER 1536
#define DK    128
#define BATCH 4
#define SEQ   2048
#define MTOT  (BATCH*SEQ)          // 8192
#define NCOLS (2*INTER+DK)         // 3200
#define LOG512F 6.2383246250395075f
#define GEMM_SMEM (3*4*512*16)     // 96 KB: 3 stages x 4 tiles x 8KB

typedef unsigned short u16;

// ---------------- scratch (device globals) ---------------------------------
__device__ u16   g_Hh[(size_t)MTOT*HID],   g_Hl[(size_t)MTOT*HID];
__device__ u16   g_Wih[(size_t)HID*NCOLS], g_Wil[(size_t)HID*NCOLS];
__device__ u16   g_Woh[(size_t)INTER*HID], g_Wol[(size_t)INTER*HID];
__device__ float g_u[(size_t)MTOT*INTER];
__device__ u16   g_vh[(size_t)MTOT*INTER], g_vl[(size_t)MTOT*INTER];
__device__ u16   g_qh[(size_t)MTOT*DK],    g_ql[(size_t)MTOT*DK];
__device__ u16   g_kh[(size_t)MTOT*DK],    g_kl[(size_t)MTOT*DK];
__device__ float g_A [(size_t)BATCH*SEQ*SEQ];
__device__ u16   g_Ah[(size_t)BATCH*SEQ*SEQ], g_Al[(size_t)BATCH*SEQ*SEQ];
__device__ u16   g_th[(size_t)MTOT*INTER], g_tl[(size_t)MTOT*INTER];

// ---------------- PTX helpers ----------------------------------------------
__device__ __forceinline__ void mma16816(float c[4], const unsigned a[4], const unsigned b[2]) {
    asm volatile(
        "mma.sync.aligned.m16n8k16.row.col.f32.bf16.bf16.f32 "
        "{%0,%1,%2,%3}, {%4,%5,%6,%7}, {%8,%9}, {%0,%1,%2,%3};\n"
        : "+f"(c[0]), "+f"(c[1]), "+f"(c[2]), "+f"(c[3])
        : "r"(a[0]), "r"(a[1]), "r"(a[2]), "r"(a[3]), "r"(b[0]), "r"(b[1]));
}
__device__ __forceinline__ void ldsm4(unsigned r[4], unsigned addr) {
    asm volatile("ldmatrix.sync.aligned.m8n8.x4.shared.b16 {%0,%1,%2,%3}, [%4];\n"
        : "=r"(r[0]), "=r"(r[1]), "=r"(r[2]), "=r"(r[3]) : "r"(addr));
}
__device__ __forceinline__ void ldsm4t(unsigned r[4], unsigned addr) {
    asm volatile("ldmatrix.sync.aligned.m8n8.x4.trans.shared.b16 {%0,%1,%2,%3}, [%4];\n"
        : "=r"(r[0]), "=r"(r[1]), "=r"(r[2]), "=r"(r[3]) : "r"(addr));
}
__device__ __forceinline__ void cp16(void* dst, const void* src) {
    unsigned d = (unsigned)__cvta_generic_to_shared(dst);
    asm volatile("cp.async.cg.shared.global [%0], [%1], 16;\n" :: "r"(d), "l"(src));
}
__device__ __forceinline__ void splitf(float x, u16& h, u16& l) {
    __nv_bfloat16 hb = __float2bfloat16(x);
    h = __bfloat16_as_ushort(hb);
    l = __bfloat16_as_ushort(__float2bfloat16(x - __bfloat162float(hb)));
}

// ---------------- input pre-split kernel ------------------------------------
__global__ __launch_bounds__(256)
void k_splitsel(const float4* __restrict__ src, int which, int n4)
{
    int i = blockIdx.x * 256 + threadIdx.x;
    if (i >= n4) return;
    ushort4* h4; ushort4* l4;
    if (which == 0)      { h4 = (ushort4*)g_Hh;  l4 = (ushort4*)g_Hl;  }
    else if (which == 1) { h4 = (ushort4*)g_Wih; l4 = (ushort4*)g_Wil; }
    else                 { h4 = (ushort4*)g_Woh; l4 = (ushort4*)g_Wol; }
    float4 f = src[i];
    ushort4 H, L;
    splitf(f.x, H.x, L.x); splitf(f.y, H.y, L.y);
    splitf(f.z, H.z, L.z); splitf(f.w, H.w, L.w);
    h4[i] = H; l4[i] = L;
}

// ---------------- tile stagers (cp.async) -----------------------------------
// A-style tile: 128 rows x 32 k, bf16, row stride 64B (4 chunks), swizzle c^=(row>>1)&3
__device__ __forceinline__ void stage_tileA(uint4* dst, const u16* __restrict__ g,
                                            int ld, int tid) {
    #pragma unroll
    for (int r = 0; r < 2; r++) {
        int c = tid + r * 256;
        int row = c >> 2, kc = c & 3;
        cp16(dst + row * 4 + (kc ^ ((row >> 1) & 3)),
             g + (size_t)row * ld + kc * 8);
    }
}
// B-style tile: 32 k-rows x 128 n, bf16, row stride 256B (16 chunks), swizzle c^=k&7
__device__ __forceinline__ void stage_tileB(uint4* dst, const u16* __restrict__ g,
                                            int ld, int tid) {
    #pragma unroll
    for (int r = 0; r < 2; r++) {
        int c = tid + r * 256;
        int k = c >> 4, nc = c & 15;
        cp16(dst + k * 16 + (nc ^ (k & 7)),
             g + (size_t)k * ld + nc * 8);
    }
}

// ---------------- bf16x3 tensor-core GEMM body (pre-split operands) ---------
// 128x128 CTA tile, BK=32, 256 threads, warps 2(m) x 4(n), warp tile 64x32.
// 3-stage cp.async pipeline, prefetch distance 2, ONE __syncthreads per chunk.
// BT=true: B stored [N][K] (Q@K^T).
template<bool BT>
__device__ __forceinline__ void mma_gemm_pk(const u16* __restrict__ Ah, const u16* __restrict__ Al, int lda,
                                            const u16* __restrict__ Bh, const u16* __restrict__ Bl, int ldb,
                                            int K, int rowBase, int colBase,
                                            float acc[4][4][4])
{
    extern __shared__ __align__(16) uint4 smdyn[];
    const int tid = threadIdx.x;
    const int lane = tid & 31, w = tid >> 5;
    const int wm = w >> 2, wn = w & 3;
    const int g = lane >> 3, i = lane & 7;
    const int nsteps = K / 32;

    auto issue = [&](int step) {
        uint4* st = smdyn + (step % 3) * 2048;
        int k0 = step * 32;
        stage_tileA(st,        Ah + (size_t)rowBase * lda + k0, lda, tid);
        stage_tileA(st + 512,  Al + (size_t)rowBase * lda + k0, lda, tid);
        if (BT) {
            stage_tileA(st + 1024, Bh + (size_t)colBase * ldb + k0, ldb, tid);
            stage_tileA(st + 1536, Bl + (size_t)colBase * ldb + k0, ldb, tid);
        } else {
            stage_tileB(st + 1024, Bh + (size_t)k0 * ldb + colBase, ldb, tid);
            stage_tileB(st + 1536, Bl + (size_t)k0 * ldb + colBase, ldb, tid);
        }
        asm volatile("cp.async.commit_group;\n");
    };

    issue(0);
    issue(1);
    for (int step = 0; step < nsteps; step++) {
        if (step + 1 < nsteps)
            asm volatile("cp.async.wait_group 1;\n");
        else
            asm volatile("cp.async.wait_group 0;\n");
        __syncthreads();

        const uint4* st = smdyn + (step % 3) * 2048;
        const unsigned bAh = (unsigned)__cvta_generic_to_shared(st);
        const unsigned bAl = bAh + 8192;
        const unsigned bBh = bAh + 16384;
        const unsigned bBl = bAh + 24576;

        #pragma unroll
        for (int ks = 0; ks < 32; ks += 16) {
            unsigned aH[4][4], aL[4][4];
            #pragma unroll
            for (int mi = 0; mi < 4; mi++) {
                int mrow = wm * 64 + mi * 16 + (g & 1) * 8 + i;
                int ch = (ks >> 3) + (g >> 1);
                int off = mrow * 64 + ((ch ^ ((mrow >> 1) & 3)) << 4);
                ldsm4(aH[mi], bAh + off);
                ldsm4(aL[mi], bAl + off);
            }
            unsigned bH[4][2], bL[4][2];
            #pragma unroll
            for (int p = 0; p < 2; p++) {
                unsigned rh[4], rl[4];
                if (BT) {
                    int nrow = wn * 32 + p * 16 + (g >> 1) * 8 + i;
                    int ch = (ks >> 3) + (g & 1);
                    int off = nrow * 64 + ((ch ^ ((nrow >> 1) & 3)) << 4);
                    ldsm4(rh, bBh + off);
                    ldsm4(rl, bBl + off);
                } else {
                    int kr = ks + (g & 1) * 8 + i;
                    int nl = wn * 32 + p * 16 + (g >> 1) * 8;
                    int off = kr * 256 + ((((nl >> 3) ^ (kr & 7))) << 4);
                    ldsm4t(rh, bBh + off);
                    ldsm4t(rl, bBl + off);
                }
                bH[2*p][0] = rh[0]; bH[2*p][1] = rh[1];
                bH[2*p+1][0] = rh[2]; bH[2*p+1][1] = rh[3];
                bL[2*p][0] = rl[0]; bL[2*p][1] = rl[1];
                bL[2*p+1][0] = rl[2]; bL[2*p+1][1] = rl[3];
            }
            #pragma unroll
            for (int mi = 0; mi < 4; mi++)
                #pragma unroll
                for (int ng = 0; ng < 4; ng++) {
                    mma16816(acc[mi][ng], aH[mi], bH[ng]);
                    mma16816(acc[mi][ng], aH[mi], bL[ng]);
                    mma16816(acc[mi][ng], aL[mi], bH[ng]);
                }
        }
        // refill the slot we just finished reading (guarded by next iter's sync)
        if (step + 2 < nsteps) issue(step + 2);
    }
}

#define EPI_SETUP() \
    const int lane = threadIdx.x & 31, w = threadIdx.x >> 5; \
    const int wm = w >> 2, wn = w & 3; \
    const int er = lane >> 2, ec = (lane & 3) * 2;

// ---------------- kernel 1: GEMM1 + SiLU + split ---------------------------
__global__ __launch_bounds__(256)
void k_gemm1(const float* __restrict__ qg, const float* __restrict__ kg)
{
    float acc[4][4][4] = {};
    const int rowBase = blockIdx.y * 128, colBase = blockIdx.x * 128;
    mma_gemm_pk<false>(g_Hh, g_Hl, HID, g_Wih, g_Wil, NCOLS, HID, rowBase, colBase, acc);
    EPI_SETUP();
    #pragma unroll
    for (int mi = 0; mi < 4; mi++)
        #pragma unroll
        for (int ng = 0; ng < 4; ng++) {
            int r0 = rowBase + wm * 64 + mi * 16 + er;
            int c0 = colBase + wn * 32 + ng * 8 + ec;
            #pragma unroll
            for (int h = 0; h < 2; h++) {
                int row = r0 + h * 8;
                #pragma unroll
                for (int j = 0; j < 2; j++) {
                    int col = c0 + j;
                    float x = acc[mi][ng][h * 2 + j];
                    float v = x / (1.0f + __expf(-x));  // SiLU
                    if (col < INTER) {
                        g_u[(size_t)row * INTER + col] = v;
                    } else if (col < 2 * INTER) {
                        size_t idx = (size_t)row * INTER + (col - INTER);
                        splitf(v, g_vh[idx], g_vl[idx]);
                    } else {
                        int c = col - 2 * INTER;
                        size_t idx = (size_t)row * DK + c;
                        splitf(v * qg[c], g_qh[idx], g_ql[idx]);
                        splitf(v * kg[c], g_kh[idx], g_kl[idx]);
                    }
                }
            }
        }
}

// ---------------- kernel 2: Q @ K^T / sqrt(DK) -----------------------------
__global__ __launch_bounds__(256)
void k_qk()
{
    float acc[4][4][4] = {};
    const int b = blockIdx.z;
    const int rowBase = blockIdx.y * 128, colBase = blockIdx.x * 128;
    const size_t o = (size_t)b * SEQ * DK;
    mma_gemm_pk<true>(g_qh + o, g_ql + o, DK, g_kh + o, g_kl + o, DK,
                      DK, rowBase, colBase, acc);
    float* Ab = g_A + (size_t)b * SEQ * SEQ;
    const float sc = 0.08838834764831845f;  // 1/sqrt(128)
    EPI_SETUP();
    #pragma unroll
    for (int mi = 0; mi < 4; mi++)
        #pragma unroll
        for (int ng = 0; ng < 4; ng++) {
            int r0 = rowBase + wm * 64 + mi * 16 + er;
            int c0 = colBase + wn * 32 + ng * 8 + ec;
            *(float2*)&Ab[(size_t)r0 * SEQ + c0] =
                make_float2(acc[mi][ng][0] * sc, acc[mi][ng][1] * sc);
            *(float2*)&Ab[(size_t)(r0 + 8) * SEQ + c0] =
                make_float2(acc[mi][ng][2] * sc, acc[mi][ng][3] * sc);
        }
}

// ---------------- kernel 3: masked softmax, writes split bf16 --------------
__global__ __launch_bounds__(256)
void k_softmax(const int* __restrict__ mask)
{
    const int bm = blockIdx.x;
    const int b = bm >> 11;
    const int m = bm & (SEQ - 1);
    const int tid = threadIdx.x;

    __shared__ float sdata[SEQ];
    __shared__ float red[256];

    float ls = 0.f;
    for (int n = tid; n < SEQ; n += 256) ls += (float)mask[b * SEQ + n];
    red[tid] = ls; __syncthreads();
    for (int s = 128; s > 0; s >>= 1) {
        if (tid < s) red[tid] += red[tid + s];
        __syncthreads();
    }
    const float l = red[0];
    __syncthreads();
    const float scale = logf(fmaxf(l, 1.0f)) * (1.0f / LOG512F);

    const size_t rowoff = (size_t)b * SEQ * SEQ + (size_t)m * SEQ;
    const float* row = g_A + rowoff;

    float mx = -3.4e38f;
    for (int n = tid; n < SEQ; n += 256) {
        float a = row[n];
        if (mask[b * SEQ + n] == 0) a = -1e12f;
        a *= scale;
        sdata[n] = a;
        mx = fmaxf(mx, a);
    }
    red[tid] = mx; __syncthreads();
    for (int s = 128; s > 0; s >>= 1) {
        if (tid < s) red[tid] = fmaxf(red[tid], red[tid + s]);
        __syncthreads();
    }
    mx = red[0]; __syncthreads();

    float sm = 0.f;
    for (int n = tid; n < SEQ; n += 256) {
        float e = __expf(sdata[n] - mx);
        sdata[n] = e;
        sm += e;
    }
    red[tid] = sm; __syncthreads();
    for (int s = 128; s > 0; s >>= 1) {
        if (tid < s) red[tid] += red[tid + s];
        __syncthreads();
    }
    const float inv = 1.0f / red[0];
    __syncthreads();

    for (int n = tid; n < SEQ; n += 256)
        splitf(sdata[n] * inv, g_Ah[rowoff + n], g_Al[rowoff + n]);
}

// ---------------- kernel 4: (A @ V) * u, writes split t --------------------
__global__ __launch_bounds__(256)
void k_av()
{
    float acc[4][4][4] = {};
    const int b = blockIdx.z;
    const int rowBase = blockIdx.y * 128, colBase = blockIdx.x * 128;
    const size_t oa = (size_t)b * SEQ * SEQ;
    const size_t ov = (size_t)b * SEQ * INTER;
    mma_gemm_pk<false>(g_Ah + oa, g_Al + oa, SEQ, g_vh + ov, g_vl + ov, INTER,
                       SEQ, rowBase, colBase, acc);
    EPI_SETUP();
    #pragma unroll
    for (int mi = 0; mi < 4; mi++)
        #pragma unroll
        for (int ng = 0; ng < 4; ng++) {
            int r0 = rowBase + wm * 64 + mi * 16 + er;
            int c0 = colBase + wn * 32 + ng * 8 + ec;
            #pragma unroll
            for (int h = 0; h < 2; h++) {
                int row = r0 + h * 8;
                size_t base = ((size_t)(b * SEQ + row)) * INTER + c0;
                float2 u2 = *(const float2*)&g_u[base];
                splitf(u2.x * acc[mi][ng][h * 2],     g_th[base],     g_tl[base]);
                splitf(u2.y * acc[mi][ng][h * 2 + 1], g_th[base + 1], g_tl[base + 1]);
            }
        }
}

// ---------------- kernel 5: t @ Wo -> out ----------------------------------
__global__ __launch_bounds__(256)
void k_out(float* __restrict__ out)
{
    float acc[4][4][4] = {};
    const int rowBase = blockIdx.y * 128, colBase = blockIdx.x * 128;
    mma_gemm_pk<false>(g_th, g_tl, INTER, g_Woh, g_Wol, HID,
                       INTER, rowBase, colBase, acc);
    EPI_SETUP();
    #pragma unroll
    for (int mi = 0; mi < 4; mi++)
        #pragma unroll
        for (int ng = 0; ng < 4; ng++) {
            int r0 = rowBase + wm * 64 + mi * 16 + er;
            int c0 = colBase + wn * 32 + ng * 8 + ec;
            *(float2*)&out[(size_t)r0 * HID + c0] =
                make_float2(acc[mi][ng][0], acc[mi][ng][1]);
            *(float2*)&out[(size_t)(r0 + 8) * HID + c0] =
                make_float2(acc[mi][ng][2], acc[mi][ng][3]);
        }
}

// ---------------- launch ----------------------------------------------------
extern "C" void kernel_launch(void* const* d_in, const int* in_sizes, int n_in,
                              void* d_out, int out_size)
{
    const float* h    = (const float*)d_in[0];
    const float* Wi   = (const float*)d_in[1];
    const float* Wo   = (const float*)d_in[2];
    const float* qg   = (const float*)d_in[3];
    const float* kg   = (const float*)d_in[4];
    const int*   mask = (const int*)d_in[5];
    float*       out  = (float*)d_out;

    cudaFuncSetAttribute(k_gemm1, cudaFuncAttributeMaxDynamicSharedMemorySize, GEMM_SMEM);
    cudaFuncSetAttribute(k_qk,    cudaFuncAttributeMaxDynamicSharedMemorySize, GEMM_SMEM);
    cudaFuncSetAttribute(k_av,    cudaFuncAttributeMaxDynamicSharedMemorySize, GEMM_SMEM);
    cudaFuncSetAttribute(k_out,   cudaFuncAttributeMaxDynamicSharedMemorySize, GEMM_SMEM);

    int n4h  = MTOT * HID / 4;
    int n4wi = HID * NCOLS / 4;
    int n4wo = INTER * HID / 4;
    k_splitsel<<<(n4h  + 255) / 256, 256>>>((const float4*)h,  0, n4h);
    k_splitsel<<<(n4wi + 255) / 256, 256>>>((const float4*)Wi, 1, n4wi);
    k_splitsel<<<(n4wo + 255) / 256, 256>>>((const float4*)Wo, 2, n4wo);

    k_gemm1<<<dim3(NCOLS / 128, MTOT / 128), 256, GEMM_SMEM>>>(qg, kg);
    k_qk<<<dim3(SEQ / 128, SEQ / 128, BATCH), 256, GEMM_SMEM>>>();
    k_softmax<<<BATCH * SEQ, 256>>>(mask);
    k_av<<<dim3(INTER / 128, SEQ / 128, BATCH), 256, GEMM_SMEM>>>();
    k_out<<<dim3(HID / 128, MTOT / 128), 256, GEMM_SMEM>>>(out);
}